// round 7
// baseline (speedup 1.0000x reference)
#include <cuda_runtime.h>
#include <cuda_bf16.h>
#include <math.h>
#include <stddef.h>
#include <stdint.h>

// Problem constants
#define B_  2
#define S_  2048
#define D_  1024
#define H_  16
#define FK_ 32
#define DK_ 64
#define BH_ (B_*H_)

#define CAP_HALF 128          // per half-row candidate cap (gmem segment)

// ---------------- scratch (__device__ globals; no allocation allowed) ----------------
__device__ float g_M[H_*DK_*DK_];
__device__ float g_Qp[B_*S_*D_];          // [B,S,D] (h*64+d)
__device__ float g_vp[B_*S_*D_];          // v@Wv+bv
__device__ float g_concat[B_*S_*D_];      // attention output pre-Wo
// bf16 per-head K-major copies: [bh][s][64]
__device__ __nv_bfloat16 g_Abf[BH_*S_*DK_];
__device__ __nv_bfloat16 g_Bbf[BH_*S_*DK_];
// candidate lists per (bh,s) row: two half-segments of CAP_HALF each
__device__ int g_ct[(size_t)BH_*S_*2*CAP_HALF];
__device__ int g_cn[BH_*S_*2];            // TRUE counts (may exceed CAP_HALF -> flagged)

// ---------------- warp-MMA helpers (sm_80-era PTX; SASS = HMMA) ----------------
__device__ __forceinline__ uint32_t smem_u32(const void* p) {
    uint32_t a;
    asm("{ .reg .u64 t; cvta.to.shared.u64 t, %1; cvt.u32.u64 %0, t; }" : "=r"(a) : "l"(p));
    return a;
}
__device__ __forceinline__ void ldmx4(uint32_t* r, uint32_t addr) {
    asm volatile("ldmatrix.sync.aligned.m8n8.x4.shared.b16 {%0,%1,%2,%3}, [%4];"
                 : "=r"(r[0]), "=r"(r[1]), "=r"(r[2]), "=r"(r[3]) : "r"(addr));
}
__device__ __forceinline__ void ldmx2(uint32_t* r, uint32_t addr) {
    asm volatile("ldmatrix.sync.aligned.m8n8.x2.shared.b16 {%0,%1}, [%2];"
                 : "=r"(r[0]), "=r"(r[1]) : "r"(addr));
}
__device__ __forceinline__ void mma_bf16(float* c, const uint32_t* a, const uint32_t* b) {
    asm volatile(
        "mma.sync.aligned.m16n8k16.row.col.f32.bf16.bf16.f32 "
        "{%0,%1,%2,%3}, {%4,%5,%6,%7}, {%8,%9}, {%0,%1,%2,%3};"
        : "+f"(c[0]), "+f"(c[1]), "+f"(c[2]), "+f"(c[3])
        : "r"(a[0]), "r"(a[1]), "r"(a[2]), "r"(a[3]), "r"(b[0]), "r"(b[1]));
}
// swizzled tile offset: 128 rows x 64 bf16 (128B = 8 chunks of 16B per row)
__device__ __forceinline__ uint32_t swoff(int row, int chunk) {
    return (uint32_t)(row * 128 + ((chunk ^ (row & 7)) * 16));
}

// ---------------- 1) collapse the low-rank chain per head, in fp64 ----------------
__global__ void compute_M_kernel(const float* __restrict__ W_A,
                                 const float* __restrict__ W_A2) {
    int h = blockIdx.x;
    __shared__ double T1[64*64];
    __shared__ double T2[64*32];
    const float* WAh  = W_A  + h*2048;
    const float* WA2h = W_A2 + h*2048;

    for (int idx = threadIdx.x; idx < 4096; idx += blockDim.x) {
        int c = idx >> 6, d = idx & 63;
        double acc = 0.0;
        #pragma unroll 8
        for (int j = 0; j < 32; j++)
            acc += (double)WAh[c*32 + j] * (double)WAh[j*64 + d];
        T1[idx] = acc;
    }
    __syncthreads();
    for (int idx = threadIdx.x; idx < 2048; idx += blockDim.x) {
        int c = idx >> 5, j = idx & 31;
        double acc = 0.0;
        #pragma unroll 8
        for (int d = 0; d < 64; d++)
            acc += T1[c*64 + d] * (double)WA2h[d*32 + j];
        T2[idx] = acc;
    }
    __syncthreads();
    for (int idx = threadIdx.x; idx < 4096; idx += blockDim.x) {
        int c = idx >> 6, d = idx & 63;
        double acc = 0.0;
        #pragma unroll 8
        for (int j = 0; j < 32; j++)
            acc += T2[c*32 + j] * (double)WA2h[j*64 + d];
        g_M[h*4096 + idx] = (float)acc;
    }
}

// ---------------- 2) Qp = q @ M[h] per head ----------------
__global__ void qp_kernel(const float* __restrict__ q) {
    int token = blockIdx.x;
    __shared__ float qs[D_];
    const float* qrow = q + (size_t)token * D_;
    for (int i = threadIdx.x; i < D_; i += 256) qs[i] = qrow[i];
    __syncthreads();
    int d  = threadIdx.x & 63;
    int h0 = threadIdx.x >> 6;
    float* out = g_Qp + (size_t)token * D_;
    #pragma unroll
    for (int hh = 0; hh < 4; hh++) {
        int h = h0 * 4 + hh;
        const float* Mh = g_M + h*4096;
        const float* qh = qs + h*64;
        float acc = 0.f;
        #pragma unroll 8
        for (int c = 0; c < 64; c++) acc = fmaf(qh[c], Mh[c*64 + d], acc);
        out[h*64 + d] = acc;
    }
}

// ---------------- 2b) fp32 -> bf16, per-head K-major layout ----------
__global__ void convert_bf16_kernel(const float* __restrict__ src,
                                    __nv_bfloat16* __restrict__ dst) {
    int token = blockIdx.x;                  // b*2048+s
    int b = token >> 11, s = token & 2047;
    const float* row = src + (size_t)token * D_;
    for (int i = threadIdx.x; i < D_; i += 256) {
        int h = i >> 6, d = i & 63;
        size_t o = ((size_t)((b*16 + h)*2048 + s))*64 + d;
        dst[o] = __float2bfloat16(row[i]);
    }
}

// ---------------- 3) scalar SGEMM (R1, at SIMT fp32 ceiling) ----------------
__global__ __launch_bounds__(256)
void sgemm_nn_bias(int M, int N, int K,
                   const float* __restrict__ A,
                   const float* __restrict__ Bm,
                   const float* __restrict__ bias,
                   float* __restrict__ C) {
    __shared__ float As[16][128];
    __shared__ float Bs[16][128];
    int bm = blockIdx.y * 128;
    int bn = blockIdx.x * 128;
    int tid = threadIdx.x;
    int tx = tid & 15, ty = tid >> 4;

    float acc[8][8];
    #pragma unroll
    for (int i = 0; i < 8; i++)
        #pragma unroll
        for (int j = 0; j < 8; j++) acc[i][j] = 0.f;

    int arow = tid >> 1;
    int acol = (tid & 1) * 8;
    int brow = tid >> 4;
    int bcol = (tid & 15) * 8;

    for (int k0 = 0; k0 < K; k0 += 16) {
        const float* Ap = A + (size_t)(bm + arow) * K + k0 + acol;
        float4 a0 = *(const float4*)Ap;
        float4 a1 = *(const float4*)(Ap + 4);
        As[acol+0][arow] = a0.x; As[acol+1][arow] = a0.y;
        As[acol+2][arow] = a0.z; As[acol+3][arow] = a0.w;
        As[acol+4][arow] = a1.x; As[acol+5][arow] = a1.y;
        As[acol+6][arow] = a1.z; As[acol+7][arow] = a1.w;

        const float* Bp = Bm + (size_t)(k0 + brow) * N + bn + bcol;
        *(float4*)&Bs[brow][bcol]     = *(const float4*)Bp;
        *(float4*)&Bs[brow][bcol + 4] = *(const float4*)(Bp + 4);
        __syncthreads();

        #pragma unroll
        for (int kk = 0; kk < 16; kk++) {
            float a[8], b[8];
            *(float4*)(a)     = *(float4*)&As[kk][ty*8];
            *(float4*)(a + 4) = *(float4*)&As[kk][ty*8 + 4];
            *(float4*)(b)     = *(float4*)&Bs[kk][tx*8];
            *(float4*)(b + 4) = *(float4*)&Bs[kk][tx*8 + 4];
            #pragma unroll
            for (int i = 0; i < 8; i++)
                #pragma unroll
                for (int j = 0; j < 8; j++)
                    acc[i][j] = fmaf(a[i], b[j], acc[i][j]);
        }
        __syncthreads();
    }

    #pragma unroll
    for (int i = 0; i < 8; i++) {
        int row = bm + ty*8 + i;
        float* Cp = C + (size_t)row * N + bn + tx*8;
        float o[8];
        #pragma unroll
        for (int j = 0; j < 8; j++)
            o[j] = acc[i][j] + bias[bn + tx*8 + j];
        *(float4*)(Cp)     = *(float4*)(o);
        *(float4*)(Cp + 4) = *(float4*)(o + 4);
    }
}

// ---------------- 4) HMMA scores (plain bf16) + ADAPTIVE streaming capture ----
// bf16 score error is RELATIVE to the row's score scale: E <= ~0.036*rmax.
// Capture threshold: x > rmax - (104 + 0.15*max(rmax,0)) -- monotone in the
// running max, so stream-safe. Rows whose capture count overflows CAP_HALF
// (tiny-scale rows with genuinely wide softmax support) are FLAGGED via the
// true count and handled densely in the exact pass.
#define SM_A  0
#define SM_B  16384
#define SM_SC 32768
#define SMEM_SCORES 98304

__global__ __launch_bounds__(256)
void scores_hmma_kernel() {
    extern __shared__ __align__(128) char sm[];
    uint32_t smb = smem_u32(sm);

    int tid = threadIdx.x, lane = tid & 31, wid = tid >> 5;
    int stile = blockIdx.x, bh = blockIdx.y;
    int s0 = stile * 128;

    int warp_m = wid >> 1;            // 0..3 -> 32 rows each
    int warp_n = wid & 1;             // 0..1 -> 64 cols each
    int mrow0 = warp_m * 32;
    int nbase0 = warp_n * 64;

    // ---- stage A tile, swizzled ----
    const uint4* pA = (const uint4*)(g_Abf + ((size_t)bh*2048 + s0)*64);
    for (int idx = tid; idx < 1024; idx += 256) {
        int row = idx >> 3, chunk = idx & 7;
        *(uint4*)(sm + SM_A + swoff(row, chunk)) = pA[idx];
    }
    __syncthreads();

    // ---- preload A fragments (2 mfrags x 4 ksteps x 4 regs) ----
    uint32_t afr[2][4][4];
    #pragma unroll
    for (int mf = 0; mf < 2; mf++)
        #pragma unroll
        for (int ks = 0; ks < 4; ks++) {
            int row = mrow0 + mf*16 + (lane & 7) + ((lane >> 3) & 1) * 8;
            int chunk = 2*ks + (lane >> 4);
            ldmx4(afr[mf][ks], smb + SM_A + swoff(row, chunk));
        }

    // ---- per-thread scan state: row tid>>1, col half tid&1 ----
    int myrow = tid >> 1;
    int myhalf = tid & 1;
    int rowg = bh*2048 + s0 + myrow;
    int* seg = g_ct + ((size_t)rowg * 2 + myhalf) * CAP_HALF;
    float rmax = -3.0e38f;
    int cnt = 0;

    const uint4* pB = (const uint4*)(g_Bbf + (size_t)bh*2048*64);

    float acc[2][8][4];

    for (int tt = 0; tt < 16; tt++) {
        int t0 = tt * 128;
        // stage B tile
        for (int idx = tid; idx < 1024; idx += 256) {
            int row = idx >> 3, chunk = idx & 7;
            *(uint4*)(sm + SM_B + swoff(row, chunk)) = pB[(size_t)t0*8 + idx];
        }
        __syncthreads();

        #pragma unroll
        for (int mf = 0; mf < 2; mf++)
            #pragma unroll
            for (int nf = 0; nf < 8; nf++)
                #pragma unroll
                for (int c = 0; c < 4; c++) acc[mf][nf][c] = 0.f;

        #pragma unroll
        for (int ks = 0; ks < 4; ks++) {
            #pragma unroll
            for (int nf = 0; nf < 8; nf++) {
                int row = nbase0 + nf*8 + (lane & 7);
                int chunk = 2*ks + ((lane >> 3) & 1);
                uint32_t bfr[2];
                ldmx2(bfr, smb + SM_B + swoff(row, chunk));
                #pragma unroll
                for (int mf = 0; mf < 2; mf++)
                    mma_bf16(acc[mf][nf], afr[mf][ks], bfr);
            }
        }

        // write acc -> score tile in smem (fp32, row-major 128x128)
        float* sc = (float*)(sm + SM_SC);
        #pragma unroll
        for (int mf = 0; mf < 2; mf++) {
            int r0 = mrow0 + mf*16 + (lane >> 2);
            #pragma unroll
            for (int nf = 0; nf < 8; nf++) {
                int cc = nbase0 + nf*8 + 2*(lane & 3);
                *(float2*)&sc[r0*128 + cc]     = make_float2(acc[mf][nf][0], acc[mf][nf][1]);
                *(float2*)&sc[(r0+8)*128 + cc] = make_float2(acc[mf][nf][2], acc[mf][nf][3]);
            }
        }
        __syncthreads();

        // scan my half row; ADAPTIVE threshold; stream captures to private seg
        const float* rp = sc + myrow*128 + myhalf*64;
        int tglob0 = t0 + myhalf*64;
        #pragma unroll 4
        for (int j4 = 0; j4 < 16; j4++) {
            float4 x4 = *(const float4*)(rp + j4*4);
            float xs[4] = {x4.x, x4.y, x4.z, x4.w};
            #pragma unroll
            for (int u = 0; u < 4; u++) {
                float x = xs[u];
                float thr = rmax - 104.0f - 0.15f * fmaxf(rmax, 0.0f);
                if (x > thr) {
                    if (cnt < CAP_HALF) seg[cnt] = tglob0 + j4*4 + u;
                    cnt++;
                }
                if (x > rmax) rmax = x;
            }
        }
        __syncthreads();   // before overwriting score tile / B tile next iter
    }

    g_cn[rowg*2 + myhalf] = cnt;   // true count; > CAP_HALF means "flagged"
}

// ---------------- 5) exact softmax + PV: sparse path, dense fallback ----------
__global__ __launch_bounds__(64)
void exact_softmax_pv_kernel(const float* __restrict__ q) {
    int row = blockIdx.x;                 // bh*2048 + s
    int bh = row >> 11, s = row & 2047;
    int b = bh >> 4, h = bh & 15;

    __shared__ float qp_s[64];
    __shared__ int   ts[2*CAP_HALF];
    __shared__ float ex[2*CAP_HALF];
    __shared__ float sc2[S_];             // dense fallback scores/weights
    __shared__ float red[64];
    __shared__ float s_denom;

    int tid = threadIdx.x;
    int n0 = g_cn[row*2], n1 = g_cn[row*2 + 1];

    qp_s[tid] = g_Qp[((size_t)(b*2048 + s))*D_ + h*64 + tid];
    __syncthreads();

    const float* qbase  = q    + ((size_t)b*2048)*D_ + h*64;
    const float* vpbase = g_vp + ((size_t)b*2048)*D_ + h*64;

    if (n0 > CAP_HALF || n1 > CAP_HALF) {
        // ---------- DENSE fallback (rare: tiny-scale rows, wide support) ----------
        for (int t = tid; t < S_; t += 64) {
            const float* qr = qbase + (size_t)t * D_;
            float acc = 0.f;
            #pragma unroll 16
            for (int kk = 0; kk < 64; kk++) acc = fmaf(qp_s[kk], qr[kk], acc);
            sc2[t] = acc;
        }
        __syncthreads();
        // max over 2048 (deterministic)
        float pm = -3.0e38f;
        for (int t = tid; t < S_; t += 64) pm = fmaxf(pm, sc2[t]);
        red[tid] = pm; __syncthreads();
        if (tid == 0) {
            float m = red[0];
            for (int i = 1; i < 64; i++) m = fmaxf(m, red[i]);
            red[0] = m;
        }
        __syncthreads();
        float m = red[0];
        __syncthreads();
        // exp + partial sums
        float ps = 0.f;
        for (int t = tid; t < S_; t += 64) {
            float w = expf(sc2[t] - m);
            sc2[t] = w;
            ps += w;
        }
        red[tid] = ps; __syncthreads();
        if (tid == 0) {
            float den = 0.f;
            for (int i = 0; i < 64; i++) den += red[i];
            s_denom = den;
        }
        __syncthreads();
        // dense PV: thread = d
        float o = 0.f;
        for (int t = 0; t < S_; t++) {
            float w = sc2[t];
            if (w != 0.0f) o = fmaf(w, vpbase[(size_t)t * D_ + tid], o);
        }
        g_concat[((size_t)(b*2048 + s))*D_ + h*64 + tid] = o / s_denom;
        return;
    }

    // ---------- SPARSE path ----------
    int n = n0 + n1;
    const int* seg0 = g_ct + (size_t)row * 2 * CAP_HALF;
    for (int i = tid; i < n0; i += 64) ts[i]      = seg0[i];
    for (int i = tid; i < n1; i += 64) ts[n0 + i] = seg0[CAP_HALF + i];
    __syncthreads();

    // exact fp32 rescoring of candidates
    for (int i = tid; i < n; i += 64) {
        const float* qr = qbase + (size_t)ts[i] * D_;
        float acc = 0.f;
        #pragma unroll 16
        for (int kk = 0; kk < 64; kk++) acc = fmaf(qp_s[kk], qr[kk], acc);
        ex[i] = acc;
    }
    __syncthreads();

    if (tid == 0) {
        float emax = ex[0];
        for (int i = 1; i < n; i++) emax = fmaxf(emax, ex[i]);
        float den = 0.f;
        for (int i = 0; i < n; i++) { float w = expf(ex[i] - emax); ex[i] = w; den += w; }
        s_denom = den;
    }
    __syncthreads();

    float o = 0.f;
    for (int i = 0; i < n; i++) {
        float w = ex[i];
        if (w != 0.0f)
            o = fmaf(w, vpbase[(size_t)ts[i] * D_ + tid], o);
    }
    g_concat[((size_t)(b*2048 + s))*D_ + h*64 + tid] = o / s_denom;
}

// ---------------- launcher ----------------
extern "C" void kernel_launch(void* const* d_in, const int* in_sizes, int n_in,
                              void* d_out, int out_size) {
    const float* q    = (const float*)d_in[0];
    // d_in[1] = k (unused in reference forward)
    const float* v    = (const float*)d_in[2];
    const float* Wv   = (const float*)d_in[3];
    const float* bv   = (const float*)d_in[4];
    const float* W_A  = (const float*)d_in[5];
    const float* W_A2 = (const float*)d_in[6];
    const float* Wo   = (const float*)d_in[7];
    const float* bo   = (const float*)d_in[8];
    float* out = (float*)d_out;

    float* vp;     cudaGetSymbolAddress((void**)&vp,     g_vp);
    float* concat; cudaGetSymbolAddress((void**)&concat, g_concat);
    float* Qp;     cudaGetSymbolAddress((void**)&Qp,     g_Qp);
    __nv_bfloat16 *Abf, *Bbf;
    cudaGetSymbolAddress((void**)&Abf, g_Abf);
    cudaGetSymbolAddress((void**)&Bbf, g_Bbf);

    cudaFuncSetAttribute(scores_hmma_kernel,
                         cudaFuncAttributeMaxDynamicSharedMemorySize, SMEM_SCORES);

    compute_M_kernel<<<H_, 256>>>(W_A, W_A2);
    qp_kernel<<<B_*S_, 256>>>(q);
    convert_bf16_kernel<<<B_*S_, 256>>>(Qp, Abf);
    convert_bf16_kernel<<<B_*S_, 256>>>(q,  Bbf);
    sgemm_nn_bias<<<dim3(D_/128, (B_*S_)/128), 256>>>(B_*S_, D_, D_, v, Wv, bv, vp);
    scores_hmma_kernel<<<dim3(S_/128, BH_), 256, SMEM_SCORES>>>();
    exact_softmax_pv_kernel<<<BH_*S_, 64>>>(q);
    sgemm_nn_bias<<<dim3(D_/128, (B_*S_)/128), 256>>>(B_*S_, D_, D_, concat, Wo, bo, out);
}